// round 1
// baseline (speedup 1.0000x reference)
#include <cuda_runtime.h>
#include <math.h>

#define NTOK   4096
#define DMODEL 1024
#define DHID   256
#define NHEADS 4
#define HDIM   256
#define QTILE  64
#define KTILE  64

// scratch (no allocation allowed -> __device__ globals)
__device__ float g_h[NTOK * DHID];
__device__ int   g_mask[NTOK];
__device__ float g_qp[NTOK * DMODEL];
__device__ float g_kp[NTOK * DMODEL];
__device__ float g_vp[NTOK * DMODEL];
__device__ float g_ctx[NTOK * DMODEL];

enum { EPI_NONE = 0, EPI_RELU = 1, EPI_MASK = 2 };

// ---------------------------------------------------------------------------
// Tiled SGEMM: C[M,N] = A[M,K] @ B[K,N] + bias, optional relu / row-mask-zero
// BM=BN=128, BK=8, 256 threads, 8x8 per thread. All dims divide tiles here.
// ---------------------------------------------------------------------------
template <int EPI>
__global__ __launch_bounds__(256) void sgemm_k(
    const float* __restrict__ A, const float* __restrict__ B,
    const float* __restrict__ bias, float* __restrict__ C,
    int M, int N, int K, const int* __restrict__ mask)
{
    __shared__ float As[8][128];
    __shared__ float Bs[8][128];

    const int tid = threadIdx.x;
    const int bm = blockIdx.y * 128;
    const int bn = blockIdx.x * 128;

    const int arow = tid >> 1;
    const int acol = (tid & 1) * 4;
    const int brow = tid >> 5;
    const int bcol = (tid & 31) * 4;
    const int ty = tid >> 4;
    const int tx = tid & 15;

    float acc[8][8] = {};

    for (int k0 = 0; k0 < K; k0 += 8) {
        float4 av = *(const float4*)&A[(bm + arow) * K + k0 + acol];
        As[acol + 0][arow] = av.x;
        As[acol + 1][arow] = av.y;
        As[acol + 2][arow] = av.z;
        As[acol + 3][arow] = av.w;
        *(float4*)&Bs[brow][bcol] =
            *(const float4*)&B[(k0 + brow) * N + bn + bcol];
        __syncthreads();

#pragma unroll
        for (int kk = 0; kk < 8; kk++) {
            float af[8], bf[8];
            *(float4*)&af[0] = *(const float4*)&As[kk][ty * 8];
            *(float4*)&af[4] = *(const float4*)&As[kk][ty * 8 + 4];
            *(float4*)&bf[0] = *(const float4*)&Bs[kk][tx * 8];
            *(float4*)&bf[4] = *(const float4*)&Bs[kk][tx * 8 + 4];
#pragma unroll
            for (int i = 0; i < 8; i++)
#pragma unroll
                for (int j = 0; j < 8; j++)
                    acc[i][j] += af[i] * bf[j];
        }
        __syncthreads();
    }

#pragma unroll
    for (int i = 0; i < 8; i++) {
        const int row = bm + ty * 8 + i;
        int keep = 1;
        if (EPI == EPI_MASK) keep = mask[row];
#pragma unroll
        for (int j4 = 0; j4 < 8; j4 += 4) {
            float4 o;
            float v0 = acc[i][j4 + 0] + bias[bn + tx * 8 + j4 + 0];
            float v1 = acc[i][j4 + 1] + bias[bn + tx * 8 + j4 + 1];
            float v2 = acc[i][j4 + 2] + bias[bn + tx * 8 + j4 + 2];
            float v3 = acc[i][j4 + 3] + bias[bn + tx * 8 + j4 + 3];
            if (EPI == EPI_RELU) {
                v0 = fmaxf(v0, 0.f); v1 = fmaxf(v1, 0.f);
                v2 = fmaxf(v2, 0.f); v3 = fmaxf(v3, 0.f);
            }
            if (EPI == EPI_MASK && !keep) { v0 = v1 = v2 = v3 = 0.f; }
            o.x = v0; o.y = v1; o.z = v2; o.w = v3;
            *(float4*)&C[row * N + bn + tx * 8 + j4] = o;
        }
    }
}

// ---------------------------------------------------------------------------
// scores = sigmoid(h @ w2 + b2) > 0.15 -> mask.  One warp per token.
// ---------------------------------------------------------------------------
__global__ void score_k(const float* __restrict__ h,
                        const float* __restrict__ w2,
                        const float* __restrict__ b2,
                        int* __restrict__ mask)
{
    const int warp = (blockIdx.x * blockDim.x + threadIdx.x) >> 5;
    const int lane = threadIdx.x & 31;
    if (warp >= NTOK) return;
    const float* hr = h + warp * DHID;
    float s = 0.f;
#pragma unroll
    for (int i = 0; i < DHID / 32; i++)
        s += hr[lane + i * 32] * w2[lane + i * 32];
#pragma unroll
    for (int o = 16; o; o >>= 1) s += __shfl_xor_sync(0xffffffffu, s, o);
    if (lane == 0) {
        float x = s + b2[0];
        float sig = 1.0f / (1.0f + expf(-x));
        mask[warp] = (sig > 0.15f) ? 1 : 0;
    }
}

// ---------------------------------------------------------------------------
// Flash attention, fp32. One block = 64 queries x 1 head. Key tiles of 64.
// Q,K stored d-major (transposed) in smem for conflict-free S GEMM; the K
// buffer is reused for V (row-major) after S is computed.
// ---------------------------------------------------------------------------
#define QT_STR 68   // Qt/Kt row stride (d-major: [256][68])
#define VS_STR 272  // Vs row stride   (row-major: [64][272]); 64*272 == 256*68
#define SS_STR 68
#define ATTN_SMEM ((256 * QT_STR + 64 * VS_STR + 64 * SS_STR + 3 * 64) * 4 + 64 * 4)

__global__ __launch_bounds__(256, 1) void attn_k(
    const float* __restrict__ qp, const float* __restrict__ kp,
    const float* __restrict__ vp, const int* __restrict__ mask,
    float* __restrict__ ctx)
{
    extern __shared__ float sm[];
    float* Qt   = sm;                    // [256][QT_STR]  Qt[d*68+q]
    float* KV   = Qt + 256 * QT_STR;     // Kt[d*68+j] OR Vs[j*272+d]
    float* Ss   = KV + 64 * VS_STR;      // [64][SS_STR]
    float* mrow = Ss + 64 * SS_STR;
    float* lrow = mrow + 64;
    float* arow = lrow + 64;
    int*   tmsk = (int*)(arow + 64);

    const int tid  = threadIdx.x;
    const int q0   = blockIdx.x * QTILE;
    const int hoff = blockIdx.y * HDIM;

    const float scale = 0.0625f;  // 1/sqrt(256)

    // load Q tile (transposed, scaled)
#pragma unroll
    for (int it = 0; it < 16; it++) {
        int lin = tid + it * 256;     // float4 index within 64x256 tile
        int r   = lin >> 6;
        int c4  = lin & 63;
        float4 v = *(const float4*)&qp[(q0 + r) * DMODEL + hoff + c4 * 4];
        int d = c4 * 4;
        Qt[(d + 0) * QT_STR + r] = v.x * scale;
        Qt[(d + 1) * QT_STR + r] = v.y * scale;
        Qt[(d + 2) * QT_STR + r] = v.z * scale;
        Qt[(d + 3) * QT_STR + r] = v.w * scale;
    }
    if (tid < 64) { mrow[tid] = -1e30f; lrow[tid] = 0.f; }

    const int ty = tid >> 4;   // query group (4 rows) for S and O
    const int tx = tid & 15;   // key group for S / dim group for O

    float O[4][16] = {};

    for (int kt = 0; kt < NTOK / KTILE; kt++) {
        const int k0 = kt * KTILE;

        // load K tile (transposed) + tile mask
#pragma unroll
        for (int it = 0; it < 16; it++) {
            int lin = tid + it * 256;
            int r   = lin >> 6;
            int c4  = lin & 63;
            float4 v = *(const float4*)&kp[(k0 + r) * DMODEL + hoff + c4 * 4];
            int d = c4 * 4;
            KV[(d + 0) * QT_STR + r] = v.x;
            KV[(d + 1) * QT_STR + r] = v.y;
            KV[(d + 2) * QT_STR + r] = v.z;
            KV[(d + 3) * QT_STR + r] = v.w;
        }
        if (tid < 64) tmsk[tid] = mask[k0 + tid];
        __syncthreads();

        // S[64,64] = Q Kt  (each thread 4x4)
        float acc[4][4] = {};
#pragma unroll 4
        for (int k = 0; k < HDIM; k++) {
            float qf[4], kf[4];
            *(float4*)qf = *(const float4*)&Qt[k * QT_STR + ty * 4];
            *(float4*)kf = *(const float4*)&KV[k * QT_STR + tx * 4];
#pragma unroll
            for (int i = 0; i < 4; i++)
#pragma unroll
                for (int j = 0; j < 4; j++)
                    acc[i][j] += qf[i] * kf[j];
        }
#pragma unroll
        for (int i = 0; i < 4; i++)
#pragma unroll
            for (int j = 0; j < 4; j++) {
                int kc = tx * 4 + j;
                Ss[(ty * 4 + i) * SS_STR + kc] = tmsk[kc] ? acc[i][j] : -1e9f;
            }
        __syncthreads();

        // load V tile (row-major) into KV; in parallel 64 threads do softmax stats
#pragma unroll
        for (int it = 0; it < 16; it++) {
            int lin = tid + it * 256;
            int r   = lin >> 6;
            int c4  = lin & 63;
            float4 v = *(const float4*)&vp[(k0 + r) * DMODEL + hoff + c4 * 4];
            *(float4*)&KV[r * VS_STR + c4 * 4] = v;
        }
        if (tid < 64) {
            float mo = mrow[tid];
            float rm = mo;
#pragma unroll 8
            for (int j = 0; j < 64; j++) rm = fmaxf(rm, Ss[tid * SS_STR + j]);
            float a = __expf(mo - rm);
            float sum = 0.f;
#pragma unroll 8
            for (int j = 0; j < 64; j++) {
                float p = __expf(Ss[tid * SS_STR + j] - rm);
                Ss[tid * SS_STR + j] = p;
                sum += p;
            }
            lrow[tid] = lrow[tid] * a + sum;
            mrow[tid] = rm;
            arow[tid] = a;
        }
        __syncthreads();

        // rescale O, then O += P @ V  (thread: 4 queries x 16 dims)
        float al[4];
#pragma unroll
        for (int i = 0; i < 4; i++) al[i] = arow[ty * 4 + i];
#pragma unroll
        for (int i = 0; i < 4; i++)
#pragma unroll
            for (int w = 0; w < 16; w++) O[i][w] *= al[i];

        for (int j = 0; j < KTILE; j++) {
            float pv[4];
#pragma unroll
            for (int i = 0; i < 4; i++) pv[i] = Ss[(ty * 4 + i) * SS_STR + j];
            float vv[16];
#pragma unroll
            for (int w4 = 0; w4 < 4; w4++)
                *(float4*)&vv[w4 * 4] =
                    *(const float4*)&KV[j * VS_STR + tx * 16 + w4 * 4];
#pragma unroll
            for (int i = 0; i < 4; i++)
#pragma unroll
                for (int w = 0; w < 16; w++)
                    O[i][w] += pv[i] * vv[w];
        }
        __syncthreads();
    }

    // write ctx = O / l
#pragma unroll
    for (int i = 0; i < 4; i++) {
        int qi = ty * 4 + i;
        float inv = 1.0f / lrow[qi];
#pragma unroll
        for (int w4 = 0; w4 < 4; w4++) {
            float4 o;
            o.x = O[i][w4 * 4 + 0] * inv;
            o.y = O[i][w4 * 4 + 1] * inv;
            o.z = O[i][w4 * 4 + 2] * inv;
            o.w = O[i][w4 * 4 + 3] * inv;
            *(float4*)&ctx[(q0 + qi) * DMODEL + hoff + tx * 16 + w4 * 4] = o;
        }
    }
}

// ---------------------------------------------------------------------------

extern "C" void kernel_launch(void* const* d_in, const int* in_sizes, int n_in,
                              void* d_out, int out_size)
{
    const float* q  = (const float*)d_in[0];
    const float* k  = (const float*)d_in[1];
    const float* v  = (const float*)d_in[2];
    const float* w1 = (const float*)d_in[3];
    const float* b1 = (const float*)d_in[4];
    const float* w2 = (const float*)d_in[5];
    const float* b2 = (const float*)d_in[6];
    const float* wq = (const float*)d_in[7];
    const float* bq = (const float*)d_in[8];
    const float* wk = (const float*)d_in[9];
    const float* bk = (const float*)d_in[10];
    const float* wv = (const float*)d_in[11];
    const float* bv = (const float*)d_in[12];
    const float* wo = (const float*)d_in[13];
    const float* bo = (const float*)d_in[14];
    float* out = (float*)d_out;

    float *hh, *qp, *kp, *vp, *ctx;
    int* msk;
    cudaGetSymbolAddress((void**)&hh,  g_h);
    cudaGetSymbolAddress((void**)&msk, g_mask);
    cudaGetSymbolAddress((void**)&qp,  g_qp);
    cudaGetSymbolAddress((void**)&kp,  g_kp);
    cudaGetSymbolAddress((void**)&vp,  g_vp);
    cudaGetSymbolAddress((void**)&ctx, g_ctx);

    dim3 blk(256);

    // 1) predictor hidden: h = relu(q @ w1 + b1)
    sgemm_k<EPI_RELU><<<dim3(DHID / 128, NTOK / 128), blk>>>(
        q, w1, b1, hh, NTOK, DHID, DMODEL, nullptr);

    // 2) mask = sigmoid(h @ w2 + b2) > 0.15
    score_k<<<NTOK / 8, 256>>>(hh, w2, b2, msk);

    // 3) projections
    sgemm_k<EPI_NONE><<<dim3(DMODEL / 128, NTOK / 128), blk>>>(
        q, wq, bq, qp, NTOK, DMODEL, DMODEL, nullptr);
    sgemm_k<EPI_NONE><<<dim3(DMODEL / 128, NTOK / 128), blk>>>(
        k, wk, bk, kp, NTOK, DMODEL, DMODEL, nullptr);
    sgemm_k<EPI_NONE><<<dim3(DMODEL / 128, NTOK / 128), blk>>>(
        v, wv, bv, vp, NTOK, DMODEL, DMODEL, nullptr);

    // 4) flash attention with key masking
    cudaFuncSetAttribute(attn_k, cudaFuncAttributeMaxDynamicSharedMemorySize,
                         ATTN_SMEM);
    attn_k<<<dim3(NTOK / QTILE, NHEADS), blk, ATTN_SMEM>>>(qp, kp, vp, msk, ctx);

    // 5) out proj + zero inactive query rows
    sgemm_k<EPI_MASK><<<dim3(DMODEL / 128, NTOK / 128), blk>>>(
        ctx, wo, bo, out, NTOK, DMODEL, DMODEL, msk);
}

// round 3
// speedup vs baseline: 4.5910x; 4.5910x over previous
#include <cuda_runtime.h>
#include <cstdint>
#include <math.h>

#define NTOK   4096
#define DMODEL 1024
#define DHID   256
#define NHEADS 4
#define HDIM   256

// ---------------- scratch (__device__ globals; no allocation allowed) -------
__device__ float g_h  [NTOK * DHID];
__device__ int   g_mask[NTOK];
__device__ float g_qp [NTOK * DMODEL];
__device__ float g_kp [NTOK * DMODEL];
__device__ float g_vp [NTOK * DMODEL];
__device__ float g_ctx[NTOK * DMODEL];
__device__ float g_w1t[DHID * DMODEL];
__device__ float g_wqt[DMODEL * DMODEL];
__device__ float g_wkt[DMODEL * DMODEL];
__device__ float g_wvt[DMODEL * DMODEL];
__device__ float g_wot[DMODEL * DMODEL];
__device__ float g_vpt[DMODEL * NTOK];
__device__ float g_S  [(size_t)NHEADS * NTOK * NTOK];   // 268MB

// ---------------- bf16 helpers ----------------------------------------------
// pack2(x0,x1): bf16(x0) in low half, bf16(x1) in high half
__device__ __forceinline__ uint32_t pack2(float x0, float x1) {
    uint32_t r;
    asm("cvt.rn.bf16x2.f32 %0, %1, %2;" : "=r"(r) : "f"(x1), "f"(x0));
    return r;
}
// split 2 floats into bf16 hi pair + bf16 lo pair (lo = x - float(hi))
__device__ __forceinline__ void split2(float x0, float x1,
                                       uint32_t& h, uint32_t& l) {
    uint32_t hb = pack2(x0, x1);
    float f0 = __uint_as_float(hb << 16);
    float f1 = __uint_as_float(hb & 0xffff0000u);
    l = pack2(x0 - f0, x1 - f1);
    h = hb;
}

// m16n8k16 row.col f32.bf16.bf16.f32
__device__ __forceinline__ void mma16816(float* c, const uint32_t* a,
                                         const uint32_t* b) {
    asm volatile(
        "mma.sync.aligned.m16n8k16.row.col.f32.bf16.bf16.f32 "
        "{%0,%1,%2,%3}, {%4,%5,%6,%7}, {%8,%9}, {%0,%1,%2,%3};"
        : "+f"(c[0]), "+f"(c[1]), "+f"(c[2]), "+f"(c[3])
        : "r"(a[0]), "r"(a[1]), "r"(a[2]), "r"(a[3]), "r"(b[0]), "r"(b[1]));
}

// ---------------- unified 3xBF16 tensor-core GEMM ---------------------------
// D[M,N] = A[M,K] @ B[N,K]^T (+ epilogue).  CTA 128x128, K-chunk 32,
// 8 warps (4x2), warp tile 32x64.  smem rows padded to 20 u32 (80B) for
// conflict-free fragment loads.
enum { EPI_RAW = 0, EPI_BIAS, EPI_RELU, EPI_QSCALE, EPI_KEYMASK, EPI_ROWMASK };

#define SROW   20                      // u32 per smem row (16 data + 4 pad)
#define STG_U  (128 * SROW)            // u32 per sub-array (2560)
#define STG_B  (4 * STG_U * 4)         // bytes per stage: Ah|Al|Bh|Bl = 40960
#define SMEM_BYTES (2 * STG_B)         // 81920

__device__ __forceinline__ void ldg_chunk(const float* __restrict__ Arow,
                                          int lda,
                                          const float* __restrict__ Brow,
                                          int ldb, int k0, int tid,
                                          float4* av, float4* bv) {
#pragma unroll
    for (int i = 0; i < 4; i++) {
        int idx = tid + i * 256;
        int r = idx >> 3, c4 = idx & 7;
        av[i] = *(const float4*)(Arow + (long)r * lda + k0 + c4 * 4);
        bv[i] = *(const float4*)(Brow + (long)r * ldb + k0 + c4 * 4);
    }
}

__device__ __forceinline__ void sts_chunk(uint32_t* st, int tid,
                                          const float4* av, const float4* bv) {
    uint32_t* Ah = st;
    uint32_t* Al = st + STG_U;
    uint32_t* Bh = st + 2 * STG_U;
    uint32_t* Bl = st + 3 * STG_U;
#pragma unroll
    for (int i = 0; i < 4; i++) {
        int idx = tid + i * 256;
        int r = idx >> 3, c4 = idx & 7;
        uint32_t h01, l01, h23, l23;
        split2(av[i].x, av[i].y, h01, l01);
        split2(av[i].z, av[i].w, h23, l23);
        int o = r * SROW + c4 * 2;
        Ah[o] = h01; Ah[o + 1] = h23;
        Al[o] = l01; Al[o + 1] = l23;
        split2(bv[i].x, bv[i].y, h01, l01);
        split2(bv[i].z, bv[i].w, h23, l23);
        Bh[o] = h01; Bh[o + 1] = h23;
        Bl[o] = l01; Bl[o + 1] = l23;
    }
}

template <int EPI>
__global__ __launch_bounds__(256, 1) void gemm_bf(
    const float* __restrict__ A, int lda, long aZ,
    const float* __restrict__ B, int ldb, long bZ,
    float* __restrict__ C, int ldc, long cZ,
    int K, const float* __restrict__ bias,
    const int* __restrict__ mask, float scale)
{
    extern __shared__ __align__(16) char smem[];
    const int tid = threadIdx.x;
    const int wid = tid >> 5, lane = tid & 31;
    const int wm = wid & 3, wn = wid >> 2;       // 4x2 warp grid
    const int qr = lane >> 2, qc = lane & 3;
    const int bm = blockIdx.y * 128, bn = blockIdx.x * 128;

    A += blockIdx.z * aZ;
    B += blockIdx.z * bZ;
    C += blockIdx.z * cZ;
    const float* Arow = A + (long)bm * lda;
    const float* Brow = B + (long)bn * ldb;

    float acc[2][8][4];
#pragma unroll
    for (int mf = 0; mf < 2; mf++)
#pragma unroll
        for (int nf = 0; nf < 8; nf++)
#pragma unroll
            for (int j = 0; j < 4; j++) acc[mf][nf][j] = 0.f;

    const int nc = K / 32;
    float4 av[4], bv[4];

    ldg_chunk(Arow, lda, Brow, ldb, 0, tid, av, bv);
    sts_chunk((uint32_t*)smem, tid, av, bv);
    __syncthreads();

    const int arow0 = wm * 32 + qr;
    const int brow0 = wn * 64 + qr;

    for (int c = 0; c < nc; c++) {
        if (c + 1 < nc)
            ldg_chunk(Arow, lda, Brow, ldb, (c + 1) * 32, tid, av, bv);

        uint32_t* st = (uint32_t*)(smem + (c & 1) * STG_B);
        const uint32_t* Ah = st;
        const uint32_t* Al = st + STG_U;
        const uint32_t* Bh = st + 2 * STG_U;
        const uint32_t* Bl = st + 3 * STG_U;

#pragma unroll
        for (int kk = 0; kk < 2; kk++) {
            const int kof = kk * 8 + qc;
            uint32_t ah[2][4], al[2][4], bh[8][2], bl[8][2];
#pragma unroll
            for (int mf = 0; mf < 2; mf++) {
                int base = (arow0 + mf * 16) * SROW + kof;
                ah[mf][0] = Ah[base];
                ah[mf][1] = Ah[base + 8 * SROW];
                ah[mf][2] = Ah[base + 4];
                ah[mf][3] = Ah[base + 8 * SROW + 4];
                al[mf][0] = Al[base];
                al[mf][1] = Al[base + 8 * SROW];
                al[mf][2] = Al[base + 4];
                al[mf][3] = Al[base + 8 * SROW + 4];
            }
#pragma unroll
            for (int nf = 0; nf < 8; nf++) {
                int base = (brow0 + nf * 8) * SROW + kof;
                bh[nf][0] = Bh[base];
                bh[nf][1] = Bh[base + 4];
                bl[nf][0] = Bl[base];
                bl[nf][1] = Bl[base + 4];
            }
#pragma unroll
            for (int mf = 0; mf < 2; mf++)
#pragma unroll
                for (int nf = 0; nf < 8; nf++) {
                    mma16816(acc[mf][nf], ah[mf], bh[nf]);
                    mma16816(acc[mf][nf], ah[mf], bl[nf]);
                    mma16816(acc[mf][nf], al[mf], bh[nf]);
                }
        }
        __syncthreads();
        if (c + 1 < nc) {
            sts_chunk((uint32_t*)(smem + ((c + 1) & 1) * STG_B), tid, av, bv);
            __syncthreads();
        }
    }

    // ---------------- epilogue: direct float2 stores ------------------------
#pragma unroll
    for (int mf = 0; mf < 2; mf++) {
        const int r0 = bm + wm * 32 + mf * 16 + qr;
        const int r1 = r0 + 8;
        int keep0 = 1, keep1 = 1;
        if (EPI == EPI_ROWMASK) { keep0 = mask[r0]; keep1 = mask[r1]; }
#pragma unroll
        for (int nf = 0; nf < 8; nf++) {
            const int cc = bn + wn * 64 + nf * 8 + qc * 2;
            float v0 = acc[mf][nf][0], v1 = acc[mf][nf][1];
            float v2 = acc[mf][nf][2], v3 = acc[mf][nf][3];
            if (EPI == EPI_BIAS || EPI == EPI_RELU || EPI == EPI_QSCALE ||
                EPI == EPI_ROWMASK) {
                float b0 = bias[cc], b1 = bias[cc + 1];
                v0 += b0; v1 += b1; v2 += b0; v3 += b1;
            }
            if (EPI == EPI_RELU) {
                v0 = fmaxf(v0, 0.f); v1 = fmaxf(v1, 0.f);
                v2 = fmaxf(v2, 0.f); v3 = fmaxf(v3, 0.f);
            }
            if (EPI == EPI_QSCALE) {
                v0 *= scale; v1 *= scale; v2 *= scale; v3 *= scale;
            }
            if (EPI == EPI_KEYMASK) {
                if (!mask[cc])     { v0 = -1e9f; v2 = -1e9f; }
                if (!mask[cc + 1]) { v1 = -1e9f; v3 = -1e9f; }
            }
            if (EPI == EPI_ROWMASK) {
                if (!keep0) { v0 = 0.f; v1 = 0.f; }
                if (!keep1) { v2 = 0.f; v3 = 0.f; }
            }
            float2 o0 = {v0, v1}, o1 = {v2, v3};
            *(float2*)&C[(long)r0 * ldc + cc] = o0;
            *(float2*)&C[(long)r1 * ldc + cc] = o1;
        }
    }
}

// ---------------- transpose: out[C][R] = in[R][C]^T --------------------------
__global__ void transpose_k(const float* __restrict__ in, float* __restrict__ out,
                            int R, int C)
{
    __shared__ float t[32][33];
    const int bx = blockIdx.x * 32;
    const int by = blockIdx.y * 32;
#pragma unroll
    for (int j = 0; j < 32; j += 8)
        t[threadIdx.y + j][threadIdx.x] =
            in[(long)(by + threadIdx.y + j) * C + bx + threadIdx.x];
    __syncthreads();
#pragma unroll
    for (int j = 0; j < 32; j += 8)
        out[(long)(bx + threadIdx.y + j) * R + by + threadIdx.x] =
            t[threadIdx.x][threadIdx.y + j];
}

// ---------------- mask: sigmoid(h @ w2 + b2) > 0.15 --------------------------
__global__ void score_k(const float* __restrict__ h, const float* __restrict__ w2,
                        const float* __restrict__ b2, int* __restrict__ mask)
{
    const int warp = (blockIdx.x * blockDim.x + threadIdx.x) >> 5;
    const int lane = threadIdx.x & 31;
    if (warp >= NTOK) return;
    const float* hr = h + warp * DHID;
    float s = 0.f;
#pragma unroll
    for (int i = 0; i < DHID / 32; i++)
        s += hr[lane + i * 32] * w2[lane + i * 32];
#pragma unroll
    for (int o = 16; o; o >>= 1) s += __shfl_xor_sync(0xffffffffu, s, o);
    if (lane == 0) {
        float sig = 1.0f / (1.0f + expf(-(s + b2[0])));
        mask[warp] = (sig > 0.15f) ? 1 : 0;
    }
}

// ---------------- row softmax over 4096 keys (in place) ----------------------
__global__ __launch_bounds__(256) void softmax_k(float* __restrict__ S)
{
    __shared__ float cache[NTOK];
    __shared__ float red[256];
    float* Sr = S + ((size_t)blockIdx.y * NTOK + blockIdx.x) * NTOK;
    const int tid = threadIdx.x;

    float m = -3.4e38f;
#pragma unroll
    for (int i = 0; i < 4; i++) {
        float4 v = *(const float4*)&Sr[(tid + i * 256) * 4];
        m = fmaxf(m, fmaxf(fmaxf(v.x, v.y), fmaxf(v.z, v.w)));
    }
    red[tid] = m;
    __syncthreads();
    for (int s = 128; s; s >>= 1) {
        if (tid < s) red[tid] = fmaxf(red[tid], red[tid + s]);
        __syncthreads();
    }
    m = red[0];
    __syncthreads();

    float sum = 0.f;
#pragma unroll
    for (int i = 0; i < 4; i++) {
        int f4 = tid + i * 256;
        float4 v = *(const float4*)&Sr[f4 * 4];
        float4 p;
        p.x = __expf(v.x - m); p.y = __expf(v.y - m);
        p.z = __expf(v.z - m); p.w = __expf(v.w - m);
        *(float4*)&cache[f4 * 4] = p;
        sum += p.x + p.y + p.z + p.w;
    }
    red[tid] = sum;
    __syncthreads();
    for (int s = 128; s; s >>= 1) {
        if (tid < s) red[tid] += red[tid + s];
        __syncthreads();
    }
    const float inv = 1.0f / red[0];
#pragma unroll
    for (int i = 0; i < 4; i++) {
        int f4 = tid + i * 256;
        float4 p = *(float4*)&cache[f4 * 4];
        p.x *= inv; p.y *= inv; p.z *= inv; p.w *= inv;
        *(float4*)&Sr[f4 * 4] = p;
    }
}

// ---------------------------------------------------------------------------
extern "C" void kernel_launch(void* const* d_in, const int* in_sizes, int n_in,
                              void* d_out, int out_size)
{
    const float* q  = (const float*)d_in[0];
    const float* k  = (const float*)d_in[1];
    const float* v  = (const float*)d_in[2];
    const float* w1 = (const float*)d_in[3];
    const float* b1 = (const float*)d_in[4];
    const float* w2 = (const float*)d_in[5];
    const float* b2 = (const float*)d_in[6];
    const float* wq = (const float*)d_in[7];
    const float* bq = (const float*)d_in[8];
    const float* wk = (const float*)d_in[9];
    const float* bk = (const float*)d_in[10];
    const float* wv = (const float*)d_in[11];
    const float* bv = (const float*)d_in[12];
    const float* wo = (const float*)d_in[13];
    const float* bo = (const float*)d_in[14];
    float* out = (float*)d_out;

    float *hh, *qp, *kp, *vp, *ctx, *w1t, *wqt, *wkt, *wvt, *wot, *vpt, *S;
    int* msk;
    cudaGetSymbolAddress((void**)&hh,  g_h);
    cudaGetSymbolAddress((void**)&msk, g_mask);
    cudaGetSymbolAddress((void**)&qp,  g_qp);
    cudaGetSymbolAddress((void**)&kp,  g_kp);
    cudaGetSymbolAddress((void**)&vp,  g_vp);
    cudaGetSymbolAddress((void**)&ctx, g_ctx);
    cudaGetSymbolAddress((void**)&w1t, g_w1t);
    cudaGetSymbolAddress((void**)&wqt, g_wqt);
    cudaGetSymbolAddress((void**)&wkt, g_wkt);
    cudaGetSymbolAddress((void**)&wvt, g_wvt);
    cudaGetSymbolAddress((void**)&wot, g_wot);
    cudaGetSymbolAddress((void**)&vpt, g_vpt);
    cudaGetSymbolAddress((void**)&S,   g_S);

    cudaFuncSetAttribute(gemm_bf<EPI_RAW>,
        cudaFuncAttributeMaxDynamicSharedMemorySize, SMEM_BYTES);
    cudaFuncSetAttribute(gemm_bf<EPI_BIAS>,
        cudaFuncAttributeMaxDynamicSharedMemorySize, SMEM_BYTES);
    cudaFuncSetAttribute(gemm_bf<EPI_RELU>,
        cudaFuncAttributeMaxDynamicSharedMemorySize, SMEM_BYTES);
    cudaFuncSetAttribute(gemm_bf<EPI_QSCALE>,
        cudaFuncAttributeMaxDynamicSharedMemorySize, SMEM_BYTES);
    cudaFuncSetAttribute(gemm_bf<EPI_KEYMASK>,
        cudaFuncAttributeMaxDynamicSharedMemorySize, SMEM_BYTES);
    cudaFuncSetAttribute(gemm_bf<EPI_ROWMASK>,
        cudaFuncAttributeMaxDynamicSharedMemorySize, SMEM_BYTES);

    dim3 tb(32, 8);
    // weight transposes -> [N][K] row-major operands
    transpose_k<<<dim3(DHID / 32, DMODEL / 32), tb>>>(w1, w1t, DMODEL, DHID);
    transpose_k<<<dim3(32, 32), tb>>>(wq, wqt, DMODEL, DMODEL);
    transpose_k<<<dim3(32, 32), tb>>>(wk, wkt, DMODEL, DMODEL);
    transpose_k<<<dim3(32, 32), tb>>>(wv, wvt, DMODEL, DMODEL);
    transpose_k<<<dim3(32, 32), tb>>>(wo, wot, DMODEL, DMODEL);

    // 1) predictor hidden: h = relu(q @ w1 + b1)
    gemm_bf<EPI_RELU><<<dim3(DHID / 128, NTOK / 128), 256, SMEM_BYTES>>>(
        q, DMODEL, 0, w1t, DMODEL, 0, hh, DHID, 0, DMODEL, b1, nullptr, 0.f);
    // 2) token mask
    score_k<<<NTOK / 8, 256>>>(hh, w2, b2, msk);
    // 3) projections (softmax scale folded into qp)
    gemm_bf<EPI_QSCALE><<<dim3(8, 32), 256, SMEM_BYTES>>>(
        q, DMODEL, 0, wqt, DMODEL, 0, qp, DMODEL, 0, DMODEL, bq, nullptr, 0.0625f);
    gemm_bf<EPI_BIAS><<<dim3(8, 32), 256, SMEM_BYTES>>>(
        k, DMODEL, 0, wkt, DMODEL, 0, kp, DMODEL, 0, DMODEL, bk, nullptr, 0.f);
    gemm_bf<EPI_BIAS><<<dim3(8, 32), 256, SMEM_BYTES>>>(
        v, DMODEL, 0, wvt, DMODEL, 0, vp, DMODEL, 0, DMODEL, bv, nullptr, 0.f);
    // 4) transpose V projection -> [1024][4096]
    transpose_k<<<dim3(DMODEL / 32, NTOK / 32), tb>>>(vp, vpt, NTOK, DMODEL);
    // 5) S[h] = (qp*scale) @ kp^T, masked keys -> -1e9
    gemm_bf<EPI_KEYMASK><<<dim3(32, 32, NHEADS), 256, SMEM_BYTES>>>(
        qp, DMODEL, HDIM, kp, DMODEL, HDIM, S, NTOK, (long)NTOK * NTOK,
        HDIM, nullptr, msk, 0.f);
    // 6) softmax rows
    softmax_k<<<dim3(NTOK, NHEADS), 256>>>(S);
    // 7) ctx[h] = P @ V
    gemm_bf<EPI_RAW><<<dim3(HDIM / 128, 32, NHEADS), 256, SMEM_BYTES>>>(
        S, NTOK, (long)NTOK * NTOK, vpt, NTOK, (long)HDIM * NTOK,
        ctx, DMODEL, HDIM, NTOK, nullptr, nullptr, 0.f);
    // 8) out = rowmask(ctx @ wo + bo)
    gemm_bf<EPI_ROWMASK><<<dim3(8, 32), 256, SMEM_BYTES>>>(
        ctx, DMODEL, 0, wot, DMODEL, 0, out, DMODEL, 0, DMODEL, bo, msk, 0.f);
}